// round 1
// baseline (speedup 1.0000x reference)
#include <cuda_runtime.h>

#define D  512
#define TT 128
#define NN 64
#define SS 128

// ---- scratch (static device globals; no allocation) ----
__device__ float g_P[8192 * 512];        // pointer_embedding (T*N, D)
__device__ float g_qproj[384 * 512];     // src_e[0:6] @ W_obj[1024:1536]  (i*64+n, D)
__device__ float g_embproj[6 * 512];     // emb @ W_obj[512:1024]
__device__ float g_embdir[6 * 5];        // emb @ W_dir[512:1024]
__device__ float g_qdir[384 * 5];        // src_e[0:6] @ W_dir[1024:1536]
__device__ float g_rdir[384 * 5];        // src_e[0:6] @ W_dir[1536:2048]

// ============================================================
// emb projections: emb(6,512) @ W_obj[512:1024] and W_dir[512:1024]
// grid(6), block(512)
// ============================================================
__global__ void embproj_k(const float* __restrict__ emb,
                          const float* __restrict__ Wobj,
                          const float* __restrict__ Wdir) {
    __shared__ float e[D];
    int i = blockIdx.x;
    int tid = threadIdx.x;
    e[tid] = emb[i * D + tid];
    __syncthreads();
    float acc = 0.f;
    const float* wb = Wobj + (size_t)D * D + tid;   // row (512+k), col tid
    #pragma unroll 8
    for (int k = 0; k < D; k++) acc += e[k] * wb[(size_t)k * D];
    g_embproj[i * D + tid] = acc;
    if (tid < 5) {
        float a = 0.f;
        const float* wd = Wdir + (size_t)D * 5 + tid;
        for (int k = 0; k < D; k++) a += e[k] * wd[k * 5];
        g_embdir[i * 5 + tid] = a;
    }
}

// ============================================================
// per-(i,n) src_e row dotted with W_dir[1024:1536] and [1536:2048]
// grid(384), block(128)
// ============================================================
__global__ __launch_bounds__(128) void srcdir_k(const float* __restrict__ srcE,
                                                const float* __restrict__ Wdir) {
    int r = blockIdx.x;            // i*64 + n, r < 384
    int tid = threadIdx.x;
    float acc[10];
    #pragma unroll
    for (int j = 0; j < 10; j++) acc[j] = 0.f;
    const float* row = srcE + (size_t)r * D;
    for (int k = tid; k < D; k += 128) {
        float v = row[k];
        const float* w2 = Wdir + (size_t)(2 * D + k) * 5;
        const float* w3 = Wdir + (size_t)(3 * D + k) * 5;
        #pragma unroll
        for (int j = 0; j < 5; j++) {
            acc[j]     += v * w2[j];
            acc[5 + j] += v * w3[j];
        }
    }
    #pragma unroll
    for (int off = 16; off; off >>= 1)
        #pragma unroll
        for (int j = 0; j < 10; j++)
            acc[j] += __shfl_down_sync(0xffffffffu, acc[j], off);
    __shared__ float red[4][10];
    int w = tid >> 5, lane = tid & 31;
    if (lane == 0)
        #pragma unroll
        for (int j = 0; j < 10; j++) red[w][j] = acc[j];
    __syncthreads();
    if (tid < 10) {
        float s = red[0][tid] + red[1][tid] + red[2][tid] + red[3][tid];
        if (tid < 5) g_qdir[r * 5 + tid] = s;
        else         g_rdir[r * 5 + (tid - 5)] = s;
    }
}

// ============================================================
// Tiled SGEMM: C[M,512] = A[M,512] @ B[512,512]   (B row-major, ldb=512)
// 128x128 tile, K-tile 16, 256 threads, 8x8 per thread.
// mode 0: C = g_qproj (plain)
// mode 1: C = g_P, epilogue adds b_obj + gathered emb_proj + gathered q_proj
// ============================================================
__global__ __launch_bounds__(256) void sgemm_k(const float* __restrict__ A,
                                               const float* __restrict__ B,
                                               int mode,
                                               const int* __restrict__ tgt,
                                               const float* __restrict__ b_obj) {
    __shared__ __align__(16) float As[16][132];
    __shared__ __align__(16) float Bs[16][132];
    const int tid = threadIdx.x;
    const int bm = blockIdx.x * 128;
    const int bn = blockIdx.y * 128;
    const int tx = tid & 15, ty = tid >> 4;

    // A load: 128 rows x 16 k = 2048 floats, 8 per thread (2 float4)
    const int a_row = tid >> 1;
    const int a_kk  = (tid & 1) * 8;
    // B load: 16 rows x 128 cols, 8 per thread (2 float4, same row)
    const int b_kk  = tid >> 4;
    const int b_col = (tid & 15) * 8;

    float acc[8][8];
    #pragma unroll
    for (int i = 0; i < 8; i++)
        #pragma unroll
        for (int j = 0; j < 8; j++) acc[i][j] = 0.f;

    const float* aBase = A + (size_t)(bm + a_row) * D + a_kk;
    const float* bBase = B + (size_t)b_kk * D + bn + b_col;

    for (int k0 = 0; k0 < D; k0 += 16) {
        float4 av0 = *(const float4*)(aBase + k0);
        float4 av1 = *(const float4*)(aBase + k0 + 4);
        float4 bv0 = *(const float4*)(bBase + (size_t)k0 * D);
        float4 bv1 = *(const float4*)(bBase + (size_t)k0 * D + 4);
        As[a_kk + 0][a_row] = av0.x; As[a_kk + 1][a_row] = av0.y;
        As[a_kk + 2][a_row] = av0.z; As[a_kk + 3][a_row] = av0.w;
        As[a_kk + 4][a_row] = av1.x; As[a_kk + 5][a_row] = av1.y;
        As[a_kk + 6][a_row] = av1.z; As[a_kk + 7][a_row] = av1.w;
        *(float4*)&Bs[b_kk][b_col]     = bv0;
        *(float4*)&Bs[b_kk][b_col + 4] = bv1;
        __syncthreads();
        #pragma unroll
        for (int kk = 0; kk < 16; kk++) {
            float ra[8], rb[8];
            #pragma unroll
            for (int i = 0; i < 8; i++) ra[i] = As[kk][ty * 8 + i];
            #pragma unroll
            for (int j = 0; j < 8; j++) rb[j] = Bs[kk][tx * 8 + j];
            #pragma unroll
            for (int i = 0; i < 8; i++)
                #pragma unroll
                for (int j = 0; j < 8; j++) acc[i][j] += ra[i] * rb[j];
        }
        __syncthreads();
    }

    if (mode == 0) {
        #pragma unroll
        for (int i = 0; i < 8; i++) {
            int r = bm + ty * 8 + i;
            float* cp = g_qproj + (size_t)r * D + bn + tx * 8;
            #pragma unroll
            for (int j = 0; j < 8; j++) cp[j] = acc[i][j];
        }
    } else {
        #pragma unroll
        for (int i = 0; i < 8; i++) {
            int r = bm + ty * 8 + i;
            int t = r >> 6, n = r & 63;
            int tp = (t + 1) & (TT - 1);
            const int* tg = tgt + ((size_t)tp * NN + n) * 3;
            int i0 = tg[0], i1 = tg[1];
            const float* ep = g_embproj + (size_t)i0 * D;
            const float* qp = g_qproj + ((size_t)i1 * NN + n) * D;
            float* cp = g_P + (size_t)r * D;
            #pragma unroll
            for (int j = 0; j < 8; j++) {
                int c = bn + tx * 8 + j;
                cp[c] = acc[i][j] + b_obj[c] + ep[c] + qp[c];
            }
        }
    }
}

// ============================================================
// einsum('snd,tnd->tns'): per n, C(128T x 128S) = P_n @ E_n^T, K=512
// grid(64, 2): n, T-half. 64x128 tile, 256 threads, 4x8 per thread.
// Applies padding mask and writes object_selections.
// ============================================================
__global__ __launch_bounds__(256) void einsum_k(const float* __restrict__ srcE,
                                                const unsigned char* __restrict__ mask,
                                                float* __restrict__ out_obj) {
    __shared__ __align__(16) float As[16][68];    // [kk][t] t-tile 64
    __shared__ __align__(16) float Bs[16][132];   // [kk][s] s 128
    const int n  = blockIdx.x;
    const int t0 = blockIdx.y * 64;
    const int tid = threadIdx.x;
    const int tx = tid & 15, ty = tid >> 4;

    // A (g_P rows for this n): 64 x 16 = 1024 floats, 1 float4/thread
    const int a_row = tid >> 2;
    const int a_kk  = (tid & 3) * 4;
    // B (src_e rows for this n): 128 x 16 = 2048 floats, 2 float4/thread
    const int b_row = tid >> 1;
    const int b_kk  = (tid & 1) * 8;

    float acc[4][8];
    #pragma unroll
    for (int i = 0; i < 4; i++)
        #pragma unroll
        for (int j = 0; j < 8; j++) acc[i][j] = 0.f;

    const float* aBase = g_P + ((size_t)(t0 + a_row) * NN + n) * D + a_kk;
    const float* bBase = srcE + ((size_t)b_row * NN + n) * D + b_kk;

    for (int k0 = 0; k0 < D; k0 += 16) {
        float4 av  = *(const float4*)(aBase + k0);
        float4 bv0 = *(const float4*)(bBase + k0);
        float4 bv1 = *(const float4*)(bBase + k0 + 4);
        As[a_kk + 0][a_row] = av.x; As[a_kk + 1][a_row] = av.y;
        As[a_kk + 2][a_row] = av.z; As[a_kk + 3][a_row] = av.w;
        Bs[b_kk + 0][b_row] = bv0.x; Bs[b_kk + 1][b_row] = bv0.y;
        Bs[b_kk + 2][b_row] = bv0.z; Bs[b_kk + 3][b_row] = bv0.w;
        Bs[b_kk + 4][b_row] = bv1.x; Bs[b_kk + 5][b_row] = bv1.y;
        Bs[b_kk + 6][b_row] = bv1.z; Bs[b_kk + 7][b_row] = bv1.w;
        __syncthreads();
        #pragma unroll
        for (int kk = 0; kk < 16; kk++) {
            float ra[4], rb[8];
            #pragma unroll
            for (int i = 0; i < 4; i++) ra[i] = As[kk][ty * 4 + i];
            #pragma unroll
            for (int j = 0; j < 8; j++) rb[j] = Bs[kk][tx * 8 + j];
            #pragma unroll
            for (int i = 0; i < 4; i++)
                #pragma unroll
                for (int j = 0; j < 8; j++) acc[i][j] += ra[i] * rb[j];
        }
        __syncthreads();
    }

    #pragma unroll
    for (int i = 0; i < 4; i++) {
        int tt = t0 + ty * 4 + i;
        float* op = out_obj + ((size_t)tt * NN + n) * SS + tx * 8;
        #pragma unroll
        for (int j = 0; j < 8; j++) {
            int s = tx * 8 + j;
            op[j] = mask[n * SS + s] ? -__int_as_float(0x7f800000) : acc[i][j];
        }
    }
}

// ============================================================
// type_selections (6) + direction_selections (5) per (t,n) row.
// grid(8192), block(128)
// ============================================================
__global__ __launch_bounds__(128) void typedir_k(const float* __restrict__ dec,
                                                 const int* __restrict__ tgt,
                                                 const float* __restrict__ Wt,
                                                 const float* __restrict__ bt,
                                                 const float* __restrict__ Wd,
                                                 const float* __restrict__ bd,
                                                 float* __restrict__ out_type,
                                                 float* __restrict__ out_dir) {
    int r = blockIdx.x;
    int tid = threadIdx.x;
    float acc[11];
    #pragma unroll
    for (int c = 0; c < 11; c++) acc[c] = 0.f;
    const float* drow = dec + (size_t)r * D;
    for (int k = tid; k < D; k += 128) {
        float v = drow[k];
        const float* wt = Wt + (size_t)k * 6;
        #pragma unroll
        for (int c = 0; c < 6; c++) acc[c] += v * wt[c];
        const float* wd = Wd + (size_t)k * 5;
        #pragma unroll
        for (int j = 0; j < 5; j++) acc[6 + j] += v * wd[j];
    }
    #pragma unroll
    for (int off = 16; off; off >>= 1)
        #pragma unroll
        for (int c = 0; c < 11; c++)
            acc[c] += __shfl_down_sync(0xffffffffu, acc[c], off);
    __shared__ float red[4][11];
    int w = tid >> 5, lane = tid & 31;
    if (lane == 0)
        #pragma unroll
        for (int c = 0; c < 11; c++) red[w][c] = acc[c];
    __syncthreads();
    if (tid < 11) {
        float s = red[0][tid] + red[1][tid] + red[2][tid] + red[3][tid];
        int t = r >> 6, n = r & 63;
        int tp = (t + 1) & (TT - 1);
        const int* tg = tgt + ((size_t)tp * NN + n) * 3;
        if (tid < 6) {
            out_type[(size_t)r * 6 + tid] = s + bt[tid];
        } else {
            int j = tid - 6;
            out_dir[(size_t)r * 5 + j] = s + bd[j]
                + g_embdir[tg[0] * 5 + j]
                + g_qdir[((size_t)tg[1] * NN + n) * 5 + j]
                + g_rdir[((size_t)tg[2] * NN + n) * 5 + j];
        }
    }
}

// ============================================================
extern "C" void kernel_launch(void* const* d_in, const int* in_sizes, int n_in,
                              void* d_out, int out_size) {
    const float*         dec  = (const float*)d_in[0];   // (T,N,D)
    const int*           tgt  = (const int*)d_in[1];     // (T,N,3)
    const float*         srcE = (const float*)d_in[2];   // (S,N,D)
    const unsigned char* mask = (const unsigned char*)d_in[3]; // (N,S) bool
    const float*         emb  = (const float*)d_in[4];   // (6,D)
    const float*         Wt   = (const float*)d_in[5];   // (D,6)
    const float*         bt   = (const float*)d_in[6];   // (6,)
    const float*         Wo   = (const float*)d_in[7];   // (3D,D)
    const float*         bo   = (const float*)d_in[8];   // (D,)
    const float*         Wd   = (const float*)d_in[9];   // (4D,5)
    const float*         bd   = (const float*)d_in[10];  // (5,)

    float* out       = (float*)d_out;
    float* out_type  = out;                                   // (T,N,6)
    float* out_obj   = out + (size_t)TT * NN * 6;             // (T,N,S)
    float* out_dir   = out + (size_t)TT * NN * 6 + (size_t)TT * NN * SS; // (T,N,5)

    // 1. small emb projections
    embproj_k<<<6, 512>>>(emb, Wo, Wd);
    // 2. src_e row projections for direction head
    srcdir_k<<<384, 128>>>(srcE, Wd);
    // 3. q_proj = src_e[0:6 flattened, 384 rows] @ W_obj[1024:1536]
    sgemm_k<<<dim3(3, 4), 256>>>(srcE, Wo + (size_t)2 * D * D, 0, tgt, bo);
    // 4. pointer_embedding = dec @ W_obj[0:512] + gathered biases
    sgemm_k<<<dim3(64, 4), 256>>>(dec, Wo, 1, tgt, bo);
    // 5. object_selections einsum + mask
    einsum_k<<<dim3(64, 2), 256>>>(srcE, mask, out_obj);
    // 6. type + direction heads
    typedir_k<<<8192, 128>>>(dec, tgt, Wt, bt, Wd, bd, out_type, out_dir);
}